// round 12
// baseline (speedup 1.0000x reference)
#include <cuda_runtime.h>
#include <cstdint>

#define F        1024
#define F4       256
#define DOMS     8
#define NBLK     296          // 2 CTAs/SM x 148 SMs
#define TPB      256
#define TILE     32           // rows per work ticket
#define KEEPROWS 23040        // last rows kept L2-resident (~92 MB)
#define EPSV     1e-5f

// ---------------- scratch (static device globals; no allocation) ----------------
__device__ unsigned g_tickA = 0, g_tickC = 0;       // work tickets (cross-kernel reset)
__device__ float g_psum[(size_t)NBLK * DOMS * F];   // 9.7 MB (L2-resident by budget)
__device__ float g_psq [(size_t)NBLK * DOMS * F];   // 9.7 MB
__device__ int   g_pcnt[NBLK * DOMS];
__device__ float g_scale[DOMS * F];
__device__ float g_bias [DOMS * F];

// accumulate float4 vv into (SA,QA)
#define ACC(SA, QA) do { \
    SA.x += vv.x; SA.y += vv.y; SA.z += vv.z; SA.w += vv.w; \
    QA.x = fmaf(vv.x, vv.x, QA.x); QA.y = fmaf(vv.y, vv.y, QA.y); \
    QA.z = fmaf(vv.z, vv.z, QA.z); QA.w = fmaf(vv.w, vv.w, QA.w); } while (0)

#define ACC_SWITCH(D) do { switch (D) { \
    case 0: ACC(sa0, qa0); break; case 1: ACC(sa1, qa1); break; \
    case 2: ACC(sa2, qa2); break; case 3: ACC(sa3, qa3); break; \
    case 4: ACC(sa4, qa4); break; case 5: ACC(sa5, qa5); break; \
    case 6: ACC(sa6, qa6); break; default: ACC(sa7, qa7); break; } } while (0)

// group loaders: evict-first (streamed) vs default (L2-kept)
#define LOADG_CS(VB, DB, G) do { int _rr = (G) * 4; \
    _Pragma("unroll") for (int _i = 0; _i < 4; _i++) { \
        VB[_i] = __ldcs(xb + (size_t)(_rr + _i) * F4); DB[_i] = ysm[_rr + _i]; } } while (0)

#define LOADG_DF(VB, DB, G) do { int _rr = (G) * 4; \
    _Pragma("unroll") for (int _i = 0; _i < 4; _i++) { \
        VB[_i] = xb[(size_t)(_rr + _i) * F4]; DB[_i] = ysm[_rr + _i]; } } while (0)

#define CONSUME(VB, DB) do { \
    _Pragma("unroll") for (int _i = 0; _i < 4; _i++) { \
        float4 vv = VB[_i]; ACC_SWITCH(DB[_i]); } } while (0)

// double-buffered pipelined accumulate over group range [0, GEND)
#define PIPE(GEND, LOADM) do { \
    if ((GEND) > 0) { \
        LOADM(vA, dA, 0); \
        int g = 1; \
        for (; g + 1 < (GEND); g += 2) { \
            LOADM(vB, dB, g);     CONSUME(vA, dA); \
            LOADM(vA, dA, g + 1); CONSUME(vB, dB); \
        } \
        if (g < (GEND)) { LOADM(vB, dB, g); CONSUME(vA, dA); CONSUME(vB, dB); } \
        else            { CONSUME(vA, dA); } \
    } } while (0)

// ---- y dtype detection (int64 vs int32): int64 in [0,8) -> odd words zero ----
__device__ __forceinline__ int detect_is64(const void* yv, int n, int tid) {
    const unsigned* yw = (const unsigned*)yv;
    int lim = min(1024, (n - 1) / 2);
    int t = 0;
    for (int i = tid; i < lim; i += TPB)
        if (yw[2 * i + 1] != 0u) t = 1;
    return __syncthreads_or(t) ? 0 : 1;
}

// ================= K1: stats, dynamic 32-row tickets ==============================
__global__ void __launch_bounds__(TPB, 2) stats_k(
    const float4* __restrict__ x, const void* __restrict__ yv, int n)
{
    __shared__ int      ysm[TILE];
    __shared__ int      cnt[DOMS];
    __shared__ unsigned sh_t;

    const int tid = threadIdx.x;
    const int b   = blockIdx.x;
    const int NT  = (n + TILE - 1) / TILE;
    const int keep_base = max(0, n - KEEPROWS);

    if (b == 0 && tid == 0) atomicExch(&g_tickC, 0u);   // reset norm's ticket

    int is64 = detect_is64(yv, n, tid);
    if (tid < DOMS) cnt[tid] = 0;
    // (cnt visible after first loop sync)

    float4 sa0 = {0,0,0,0}, sa1 = {0,0,0,0}, sa2 = {0,0,0,0}, sa3 = {0,0,0,0};
    float4 sa4 = {0,0,0,0}, sa5 = {0,0,0,0}, sa6 = {0,0,0,0}, sa7 = {0,0,0,0};
    float4 qa0 = {0,0,0,0}, qa1 = {0,0,0,0}, qa2 = {0,0,0,0}, qa3 = {0,0,0,0};
    float4 qa4 = {0,0,0,0}, qa5 = {0,0,0,0}, qa6 = {0,0,0,0}, qa7 = {0,0,0,0};

    for (;;) {
        if (tid == 0) sh_t = atomicAdd(&g_tickA, 1u);
        __syncthreads();                    // sh_t visible; prior ysm reads done
        unsigned t = sh_t;
        if (t >= (unsigned)NT) break;
        const int base = (int)t * TILE;
        const int nr   = min(TILE, n - base);

        if (tid < nr) {
            int d = is64 ? (int)((const long long*)yv)[base + tid]
                         : ((const int*)yv)[base + tid];
            ysm[tid] = d;
            atomicAdd(&cnt[d], 1);
        }
        __syncthreads();                    // ysm ready

        const float4* xb = x + (size_t)base * F4 + tid;
        const int k = nr >> 2;
        float4 vA[4], vB[4]; int dA[4], dB[4];
        if (base >= keep_base) { PIPE(k, LOADG_DF); }   // keep-set for norm_k
        else                   { PIPE(k, LOADG_CS); }   // streamed, evict-first
        for (int r = k * 4; r < nr; r++) {
            float4 vv = xb[(size_t)r * F4];
            int d = ysm[r];
            ACC_SWITCH(d);
        }
    }

    // flush per-block partials (default policy -> L2-resident for table_k)
    float4* psum = (float4*)(g_psum + (size_t)b * DOMS * F);
    float4* psq  = (float4*)(g_psq  + (size_t)b * DOMS * F);
    psum[0 * F4 + tid] = sa0; psq[0 * F4 + tid] = qa0;
    psum[1 * F4 + tid] = sa1; psq[1 * F4 + tid] = qa1;
    psum[2 * F4 + tid] = sa2; psq[2 * F4 + tid] = qa2;
    psum[3 * F4 + tid] = sa3; psq[3 * F4 + tid] = qa3;
    psum[4 * F4 + tid] = sa4; psq[4 * F4 + tid] = qa4;
    psum[5 * F4 + tid] = sa5; psq[5 * F4 + tid] = qa5;
    psum[6 * F4 + tid] = sa6; psq[6 * F4 + tid] = qa6;
    psum[7 * F4 + tid] = sa7; psq[7 * F4 + tid] = qa7;
    if (tid < DOMS) g_pcnt[b * DOMS + tid] = cnt[tid];
}

// ================= K2: distributed partial reduce -> (scale, bias) table =========
__global__ void __launch_bounds__(TPB, 2) table_k(
    const float* __restrict__ gamma, const float* __restrict__ beta)
{
    __shared__ int   scnt[DOMS], cpart[64];
    __shared__ float sred[9][28], qred[9][28];

    const int tid = threadIdx.x;
    const int b   = blockIdx.x;

    if (b == 0 && tid == 0) atomicExch(&g_tickA, 0u);   // reset stats' ticket

    if (tid < 64) {
        int d = tid & 7, g = tid >> 3;
        int s0 = g * 37, s1 = min(NBLK, s0 + 37);
        int c = 0;
        for (int sl = s0; sl < s1; sl++) c += g_pcnt[sl * DOMS + d];
        cpart[tid] = c;
    }
    __syncthreads();
    if (tid < DOMS) {
        int c = 0;
        #pragma unroll
        for (int g = 0; g < 8; g++) c += cpart[g * 8 + tid];
        scnt[tid] = c;
    }

    const int start = b * 28;                   // 296*28 >= 8192
    const int p = tid % 28, c = tid / 28;       // c in 0..9 (c==9 idle)
    if (c < 9 && start + p < DOMS * F) {
        int j  = start + p;
        int s0 = c * 33, s1 = min(NBLK, s0 + 33);
        float ss = 0.f, qq = 0.f;
        for (int sl = s0; sl < s1; sl++) {
            ss += g_psum[(size_t)sl * (DOMS * F) + j];   // expect L2 hits
            qq += g_psq [(size_t)sl * (DOMS * F) + j];
        }
        sred[c][p] = ss; qred[c][p] = qq;
    }
    __syncthreads();
    if (tid < 28 && start + tid < DOMS * F) {
        int jj = start + tid;
        float ss = 0.f, qq = 0.f;
        #pragma unroll
        for (int cc = 0; cc < 9; cc++) { ss += sred[cc][tid]; qq += qred[cc][tid]; }
        int d = jj >> 10, f = jj & (F - 1);
        float cf = (float)scnt[d];
        float sc, bi;
        if (cf > 1.f) {
            float inv  = 1.f / cf;
            float mean = ss * inv;
            float var  = fmaxf(qq * inv - mean * mean, 0.f);
            sc = gamma[f] * rsqrtf(var + EPSV);
            bi = fmaf(-mean, sc, beta[f]);
        } else if (cf == 1.f) { sc = 1.f; bi = 0.f; }   // count==1 -> raw x
        else                  { sc = 0.f; bi = 0.f; }   // count==0 -> 0
        g_scale[jj] = sc;
        g_bias [jj] = bi;
    }
}

// ================= K3: normalize, dynamic DESCENDING tickets (L2 LIFO) ===========
__global__ void __launch_bounds__(TPB, 2) norm_k(
    const float4* __restrict__ x, const void* __restrict__ yv,
    float4* __restrict__ out, int n)
{
    __shared__ int      ysm[TILE];
    __shared__ unsigned sh_t;

    const int tid = threadIdx.x;
    const int NT  = (n + TILE - 1) / TILE;

    int is64 = detect_is64(yv, n, tid);

    const float4* sc4 = (const float4*)g_scale;
    const float4* bi4 = (const float4*)g_bias;

#define NLOAD(VB, DB, G) do { int _rr = (G) * 4; \
    _Pragma("unroll") for (int _i = 0; _i < 4; _i++) { \
        VB[_i] = __ldcs(xc + (size_t)(_rr + _i) * F4); DB[_i] = ysm[_rr + _i]; } } while (0)

#define NSTORE(VB, DB, G) do { int _rr = (G) * 4; \
    _Pragma("unroll") for (int _i = 0; _i < 4; _i++) { \
        float4 sc = sc4[DB[_i] * F4 + tid]; \
        float4 bi = bi4[DB[_i] * F4 + tid]; \
        float4 o; \
        o.x = fmaf(VB[_i].x, sc.x, bi.x); \
        o.y = fmaf(VB[_i].y, sc.y, bi.y); \
        o.z = fmaf(VB[_i].z, sc.z, bi.z); \
        o.w = fmaf(VB[_i].w, sc.w, bi.w); \
        __stcs(oc + (size_t)(_rr + _i) * F4, o); } } while (0)

    for (;;) {
        if (tid == 0) sh_t = atomicAdd(&g_tickC, 1u);
        __syncthreads();                    // sh_t visible; prior ysm reads done
        unsigned u = sh_t;
        if (u >= (unsigned)NT) break;
        const int t    = NT - 1 - (int)u;   // descending: keep-set consumed first
        const int base = t * TILE;
        const int nr   = min(TILE, n - base);

        if (tid < nr)
            ysm[tid] = is64 ? (int)((const long long*)yv)[base + tid]
                            : ((const int*)yv)[base + tid];
        __syncthreads();                    // ysm ready

        const float4* xc = x   + (size_t)base * F4 + tid;
        float4*       oc = out + (size_t)base * F4 + tid;

        const int k = nr >> 2;
        float4 vA[4], vB[4]; int dA[4], dB[4];
        if (k > 0) {
            NLOAD(vA, dA, 0);
            int g = 1;
            for (; g + 1 < k; g += 2) {
                NLOAD(vB, dB, g);     NSTORE(vA, dA, g - 1);
                NLOAD(vA, dA, g + 1); NSTORE(vB, dB, g);
            }
            if (g < k) { NLOAD(vB, dB, g); NSTORE(vA, dA, g - 1); NSTORE(vB, dB, g); }
            else       { NSTORE(vA, dA, k - 1); }
        }
        for (int r = k * 4; r < nr; r++) {
            int d = ysm[r];
            float4 v  = __ldcs(xc + (size_t)r * F4);
            float4 sc = sc4[d * F4 + tid];
            float4 bi = bi4[d * F4 + tid];
            float4 o;
            o.x = fmaf(v.x, sc.x, bi.x);
            o.y = fmaf(v.y, sc.y, bi.y);
            o.z = fmaf(v.z, sc.z, bi.z);
            o.w = fmaf(v.w, sc.w, bi.w);
            __stcs(oc + (size_t)r * F4, o);
        }
    }
}

// ---------------- launch ----------------
extern "C" void kernel_launch(void* const* d_in, const int* in_sizes, int n_in,
                              void* d_out, int out_size) {
    const float4* x     = (const float4*)d_in[0];
    const void*   y     = d_in[1];
    const float*  gamma = (const float*)d_in[2];
    const float*  beta  = (const float*)d_in[3];
    float4*       out   = (float4*)d_out;

    int n = in_sizes[1];   // batch (y element count)

    stats_k<<<NBLK, TPB>>>(x, y, n);
    table_k<<<NBLK, TPB>>>(gamma, beta);
    norm_k <<<NBLK, TPB>>>(x, y, out, n);
}